// round 10
// baseline (speedup 1.0000x reference)
#include <cuda_runtime.h>
#include <math.h>
#include <stdint.h>

#define D      512
#define B      256
#define FOURD  2048
#define QS     1024   // 2*D
#define SPLITS 8
#define NW     8      // warps per attn block (256 threads)
#define NPART  (SPLITS * NW)   // 64 partials per graph

#define BM 128
#define BN 128
#define BK 16
#define KSPLIT 8
#define KCH (QS / KSPLIT)   // 128
#define NIT (KCH / BK)      // 8

// ---- scratch (no allocations allowed) ----
__device__ float g_WcombT[QS * FOURD];  // [1024][2048] K-major (transposed combined weight)
__device__ float g_bsum[FOURD];
__device__ float g_qstar[B * QS];       // [h | r] row-major (attention/proj consumer)
__device__ float g_qstarT[QS * B];      // [1024][256] K-major (GEMM consumer)
__device__ float g_c[B * D];
__device__ float g_gpart[KSPLIT][B * FOURD];
__device__ int   g_segoff[B + 1];
// per-warp attention partials
__device__ float g_pm[B * NPART];
__device__ float g_pd[B * NPART];
__device__ float g_pr[(size_t)B * NPART * D];

__device__ __forceinline__ float sigf(float v) { return 1.0f / (1.0f + expf(-v)); }

__device__ __forceinline__ void cp_async16(uint32_t dst_smem, const void* src) {
    asm volatile("cp.async.cg.shared.global [%0], [%1], 16;" :: "r"(dst_smem), "l"(src));
}

// ---------------- fused init: WcombT transpose + bsum + step0 + segscan ----------------
#define WT_BLKS  ((FOURD / 32) * (QS / 32))   // 2048
#define STEP0_BLKS (B * D / 256)              // 512
__global__ void k_init(const void* __restrict__ raw, int N,
                       const float* __restrict__ W_ih, const float* __restrict__ W_hh,
                       const float* __restrict__ b_ih, const float* __restrict__ b_hh) {
    __shared__ float s[32][33];
    int blk = blockIdx.x;
    int t = threadIdx.x;
    if (blk < WT_BLKS) {
        int nt = blk >> 5, kt = blk & 31;
        int tx = t & 31, ty = t >> 5;
        #pragma unroll
        for (int i = 0; i < 4; i++) {
            int n = nt * 32 + ty + i * 8;
            int k = kt * 32 + tx;
            float v = W_ih[(size_t)n * QS + k];
            if (k < D) v += W_hh[(size_t)n * D + k];
            s[ty + i * 8][tx] = v;
        }
        __syncthreads();
        #pragma unroll
        for (int i = 0; i < 4; i++) {
            int k = kt * 32 + ty + i * 8;
            int n = nt * 32 + tx;
            g_WcombT[(size_t)k * FOURD + n] = s[tx][ty + i * 8];
        }
        if (blk < 8) g_bsum[blk * 256 + t] = b_ih[blk * 256 + t] + b_hh[blk * 256 + t];
    } else if (blk < WT_BLKS + STEP0_BLKS) {
        int idx = (blk - WT_BLKS) * 256 + t;
        int j = idx & (D - 1);
        float gi = b_ih[j]         + b_hh[j];
        float gg = b_ih[2 * D + j] + b_hh[2 * D + j];
        float go = b_ih[3 * D + j] + b_hh[3 * D + j];
        float c  = sigf(gi) * tanhf(gg);
        float h  = sigf(go) * tanhf(c);
        int b = idx >> 9;
        g_c[idx] = c;
        g_qstar[b * QS + j] = h;
        g_qstarT[j * B + b] = h;
    } else {
        const int* p32 = (const int*)raw;
        bool is64 = (p32[N - 1] == 0) || (p32[N - 2] == 0);
        int i = (blk - WT_BLKS - STEP0_BLKS) * 256 + t;
        if (i >= N) return;
        int cur = is64 ? (int)((const long long*)raw)[i] : p32[i];
        if (i == 0) {
            for (int j = 0; j <= cur; j++) g_segoff[j] = 0;
        } else {
            int prev = is64 ? (int)((const long long*)raw)[i - 1] : p32[i - 1];
            for (int j = prev + 1; j <= cur; j++) g_segoff[j] = i;
        }
        if (i == N - 1) {
            for (int j = cur + 1; j <= B; j++) g_segoff[j] = N;
        }
    }
}

// ---------------- LSTM elementwise, float4, 128-thr blocks ----------------
__global__ void __launch_bounds__(128) k_lstm_ew() {
    int idx = blockIdx.x * 128 + threadIdx.x;   // over B*D/4
    if (idx >= B * D / 4) return;
    int b = idx >> 7;
    int j = (idx & 127) * 4;
    float4 gi = *(const float4*)&g_bsum[j];
    float4 gf = *(const float4*)&g_bsum[D + j];
    float4 gg = *(const float4*)&g_bsum[2 * D + j];
    float4 go = *(const float4*)&g_bsum[3 * D + j];
    #pragma unroll
    for (int z = 0; z < KSPLIT; z++) {
        const float* g = &g_gpart[z][(size_t)b * FOURD];
        float4 a = *(const float4*)&g[j];
        float4 f = *(const float4*)&g[D + j];
        float4 c = *(const float4*)&g[2 * D + j];
        float4 o = *(const float4*)&g[3 * D + j];
        gi.x += a.x; gi.y += a.y; gi.z += a.z; gi.w += a.w;
        gf.x += f.x; gf.y += f.y; gf.z += f.z; gf.w += f.w;
        gg.x += c.x; gg.y += c.y; gg.z += c.z; gg.w += c.w;
        go.x += o.x; go.y += o.y; go.z += o.z; go.w += o.w;
    }
    float4 cold = *(const float4*)&g_c[b * D + j];
    float4 cnew, hnew;
    cnew.x = sigf(gf.x) * cold.x + sigf(gi.x) * tanhf(gg.x);
    cnew.y = sigf(gf.y) * cold.y + sigf(gi.y) * tanhf(gg.y);
    cnew.z = sigf(gf.z) * cold.z + sigf(gi.z) * tanhf(gg.z);
    cnew.w = sigf(gf.w) * cold.w + sigf(gi.w) * tanhf(gg.w);
    hnew.x = sigf(go.x) * tanhf(cnew.x);
    hnew.y = sigf(go.y) * tanhf(cnew.y);
    hnew.z = sigf(go.z) * tanhf(cnew.z);
    hnew.w = sigf(go.w) * tanhf(cnew.w);
    *(float4*)&g_c[b * D + j] = cnew;
    *(float4*)&g_qstar[b * QS + j] = hnew;
    g_qstarT[(j + 0) * B + b] = hnew.x;
    g_qstarT[(j + 1) * B + b] = hnew.y;
    g_qstarT[(j + 2) * B + b] = hnew.z;
    g_qstarT[(j + 3) * B + b] = hnew.w;
}

// ---------------- gates GEMM v4 (round-9 champion, unchanged) ----------------
__global__ void __launch_bounds__(256, 2) k_gemm_gates() {
    __shared__ __align__(16) float As[3][BK][BM];
    __shared__ __align__(16) float Bs[3][BK][BN];
    int n0 = blockIdx.x * BN, m0 = blockIdx.y * BM, kc = blockIdx.z * KCH;
    int t = threadIdx.x;
    int tx = t & 15, ty = t >> 4;

    unsigned long long acc2[8][4];
    #pragma unroll
    for (int i = 0; i < 8; i++)
        #pragma unroll
        for (int j = 0; j < 4; j++) acc2[i][j] = 0ull;

    int kr0 = t >> 5, kr1 = kr0 + 8;
    int mq  = (t & 31) * 4;

    const float* srcA = g_qstarT + (size_t)kc * B;
    const float* srcB = g_WcombT + (size_t)kc * FOURD;

    #pragma unroll
    for (int s = 0; s < 2; s++) {
        int kof = s * BK;
        cp_async16(__cvta_generic_to_shared(&As[s][kr0][mq]), srcA + (size_t)(kof + kr0) * B + m0 + mq);
        cp_async16(__cvta_generic_to_shared(&As[s][kr1][mq]), srcA + (size_t)(kof + kr1) * B + m0 + mq);
        cp_async16(__cvta_generic_to_shared(&Bs[s][kr0][mq]), srcB + (size_t)(kof + kr0) * FOURD + n0 + mq);
        cp_async16(__cvta_generic_to_shared(&Bs[s][kr1][mq]), srcB + (size_t)(kof + kr1) * FOURD + n0 + mq);
        asm volatile("cp.async.commit_group;");
    }

    #pragma unroll
    for (int it = 0; it < NIT; it++) {
        if (it < NIT - 1) asm volatile("cp.async.wait_group 1;");
        else              asm volatile("cp.async.wait_group 0;");
        __syncthreads();
        if (it + 2 < NIT) {
            int st = (it + 2) % 3;
            int kof = (it + 2) * BK;
            cp_async16(__cvta_generic_to_shared(&As[st][kr0][mq]), srcA + (size_t)(kof + kr0) * B + m0 + mq);
            cp_async16(__cvta_generic_to_shared(&As[st][kr1][mq]), srcA + (size_t)(kof + kr1) * B + m0 + mq);
            cp_async16(__cvta_generic_to_shared(&Bs[st][kr0][mq]), srcB + (size_t)(kof + kr0) * FOURD + n0 + mq);
            cp_async16(__cvta_generic_to_shared(&Bs[st][kr1][mq]), srcB + (size_t)(kof + kr1) * FOURD + n0 + mq);
            asm volatile("cp.async.commit_group;");
        }
        int cb = it % 3;
        #pragma unroll
        for (int kk = 0; kk < BK; kk++) {
            float a[8];
            *(float4*)(a)     = *(const float4*)&As[cb][kk][ty * 8];
            *(float4*)(a + 4) = *(const float4*)&As[cb][kk][ty * 8 + 4];
            unsigned long long b2[4];
            {
                ulonglong2 bl0 = *(const ulonglong2*)&Bs[cb][kk][tx * 8];
                ulonglong2 bl1 = *(const ulonglong2*)&Bs[cb][kk][tx * 8 + 4];
                b2[0] = bl0.x; b2[1] = bl0.y; b2[2] = bl1.x; b2[3] = bl1.y;
            }
            #pragma unroll
            for (int i = 0; i < 8; i++) {
                unsigned long long a2;
                asm("mov.b64 %0, {%1, %1};" : "=l"(a2) : "r"(__float_as_uint(a[i])));
                #pragma unroll
                for (int j = 0; j < 4; j++)
                    asm("fma.rn.f32x2 %0, %1, %2, %0;"
                        : "+l"(acc2[i][j]) : "l"(a2), "l"(b2[j]));
            }
        }
    }
    #pragma unroll
    for (int i = 0; i < 8; i++) {
        int mrow = m0 + ty * 8 + i;
        unsigned long long* dst =
            (unsigned long long*)&g_gpart[blockIdx.z][(size_t)mrow * FOURD + n0 + tx * 8];
        *(ulonglong2*)(dst)     = make_ulonglong2(acc2[i][0], acc2[i][1]);
        *(ulonglong2*)(dst + 2) = make_ulonglong2(acc2[i][2], acc2[i][3]);
    }
}

// ---------------- split segment attention: per-warp cp.async 3-slot ring ----------------
// Warp w streams nodes start+w, start+w+NW, ... through its private smem ring.
// Lane l owns cols {c*128 + l*4 .. +3}; each lane copies & reads only its own bytes,
// so only per-thread cp.async group ordering + __syncwarp are needed (no block syncs).
__global__ void __launch_bounds__(256) k_attn_part(const float* __restrict__ x) {
    __shared__ __align__(16) float xring[NW][3][D];   // 48KB

    int b  = blockIdx.x / SPLITS;
    int sp = blockIdx.x % SPLITS;
    int t = threadIdx.x;
    int w = t >> 5, lane = t & 31;

    int segs = g_segoff[b], sege = g_segoff[b + 1];
    int total = sege - segs;
    int start = segs + (int)(((long long)total * sp) / SPLITS);
    int end   = segs + (int)(((long long)total * (sp + 1)) / SPLITS);

    // q directly from global (coalesced float4 per chunk)
    float qr[16];
    #pragma unroll
    for (int c = 0; c < 4; c++) {
        float4 qv = *(const float4*)&g_qstar[b * QS + c * 128 + lane * 4];
        qr[c * 4 + 0] = qv.x; qr[c * 4 + 1] = qv.y;
        qr[c * 4 + 2] = qv.z; qr[c * 4 + 3] = qv.w;
    }

    float m = -INFINITY, d = 0.0f;
    float r[16];
    #pragma unroll
    for (int j = 0; j < 16; j++) r[j] = 0.0f;

    int n = start + w;

    // prologue: stage nodes n and n+NW into slots 0,1 (empty commits keep counts aligned)
    #pragma unroll
    for (int p = 0; p < 2; p++) {
        int ni = n + p * NW;
        if (ni < end) {
            const float* src = x + (size_t)ni * D;
            #pragma unroll
            for (int c = 0; c < 4; c++)
                cp_async16(__cvta_generic_to_shared(&xring[w][p][c * 128 + lane * 4]),
                           src + c * 128 + lane * 4);
        }
        asm volatile("cp.async.commit_group;");
    }

    int rslot = 0;
    while (n < end) {
        asm volatile("cp.async.wait_group 1;");   // node n staged; n+NW still in flight
        __syncwarp();

        float xx[16];
        #pragma unroll
        for (int c = 0; c < 4; c++) {
            float4 v = *(const float4*)&xring[w][rslot][c * 128 + lane * 4];
            xx[c * 4 + 0] = v.x; xx[c * 4 + 1] = v.y;
            xx[c * 4 + 2] = v.z; xx[c * 4 + 3] = v.w;
        }

        // stage n+2*NW into the slot consumed two iterations ago
        {
            int ni = n + 2 * NW;
            int wslot = rslot + 2 - ((rslot + 2 >= 3) ? 3 : 0);
            if (ni < end) {
                const float* src = x + (size_t)ni * D;
                #pragma unroll
                for (int c = 0; c < 4; c++)
                    cp_async16(__cvta_generic_to_shared(&xring[w][wslot][c * 128 + lane * 4]),
                               src + c * 128 + lane * 4);
            }
            asm volatile("cp.async.commit_group;");
        }

        float s = 0.0f;
        #pragma unroll
        for (int j = 0; j < 16; j++) s += xx[j] * qr[j];
        #pragma unroll
        for (int o = 16; o > 0; o >>= 1) s += __shfl_xor_sync(0xffffffffu, s, o);

        if (s > m) {
            float al = __expf(m - s);   // first iteration: exp(-inf) = 0
            d = d * al + 1.0f;
            #pragma unroll
            for (int j = 0; j < 16; j++) r[j] = r[j] * al + xx[j];
            m = s;
        } else {
            float wv = __expf(s - m);
            d += wv;
            #pragma unroll
            for (int j = 0; j < 16; j++) r[j] += wv * xx[j];
        }
        rslot = rslot + 1 - ((rslot + 1 >= 3) ? 3 : 0);
        n += NW;
    }

    // per-warp partial straight to global (canonical column order)
    int pid = (b * SPLITS + sp) * NW + w;
    float* pr = g_pr + (size_t)pid * D;
    #pragma unroll
    for (int c = 0; c < 4; c++)
        *(float4*)&pr[c * 128 + lane * 4] =
            make_float4(r[c * 4], r[c * 4 + 1], r[c * 4 + 2], r[c * 4 + 3]);
    if (lane == 0) { g_pm[pid] = m; g_pd[pid] = d; }
}

// ---------------- combine 64 per-warp partials -> r in g_qstar (+ transposed copy) ----------------
__global__ void k_attn_combine() {
    __shared__ float sm[NPART], sd[NPART], ss[NPART];
    int b = blockIdx.x, t = threadIdx.x;
    if (t < NPART) {
        sm[t] = g_pm[b * NPART + t];
        sd[t] = g_pd[b * NPART + t];
    }
    __syncthreads();
    float M = -INFINITY;
    #pragma unroll 8
    for (int p = 0; p < NPART; p++) M = fmaxf(M, sm[p]);
    float Mg = isfinite(M) ? M : 0.0f;
    if (t < NPART) ss[t] = expf(sm[t] - Mg);
    __syncthreads();
    float denom = 0.0f;
    #pragma unroll 8
    for (int p = 0; p < NPART; p++) denom += sd[p] * ss[p];
    float inv = 1.0f / (denom + 1e-16f);
    float r0 = 0.0f, r1 = 0.0f;
    #pragma unroll 4
    for (int p = 0; p < NPART; p++) {
        const float* pr = g_pr + (size_t)(b * NPART + p) * D;
        float sc = ss[p];
        r0 += pr[t]       * sc;
        r1 += pr[t + 256] * sc;
    }
    r0 *= inv; r1 *= inv;
    g_qstar[b * QS + D + t]        = r0;
    g_qstar[b * QS + D + t + 256]  = r1;
    g_qstarT[(D + t) * B + b]       = r0;
    g_qstarT[(D + t + 256) * B + b] = r1;
}

// ---------------- projection ----------------
__global__ void k_proj(const float* __restrict__ Wp, const float* __restrict__ bp,
                       float* __restrict__ out) {
    int gw = (blockIdx.x * 256 + threadIdx.x) >> 5;
    int lane = threadIdx.x & 31;
    int bb = gw >> 8, o = gw & 255;
    const float* qr = g_qstar + bb * QS;
    const float* wr = Wp + o * QS;
    float s = 0.0f;
    #pragma unroll
    for (int it = 0; it < QS / 128; it++) {
        int k = lane * 4 + it * 128;
        float4 a = *(const float4*)(qr + k);
        float4 w = *(const float4*)(wr + k);
        s += a.x * w.x + a.y * w.y + a.z * w.z + a.w * w.w;
    }
    #pragma unroll
    for (int off = 16; off > 0; off >>= 1) s += __shfl_xor_sync(0xffffffffu, s, off);
    if (lane == 0) out[gw] = s + bp[o];
}

// ---------------- launch ----------------
extern "C" void kernel_launch(void* const* d_in, const int* in_sizes, int n_in,
                              void* d_out, int out_size) {
    const float* x      = (const float*)d_in[0];
    const void*  batch  = d_in[1];
    const float* W_ih   = (const float*)d_in[2];
    const float* W_hh   = (const float*)d_in[3];
    const float* b_ih   = (const float*)d_in[4];
    const float* b_hh   = (const float*)d_in[5];
    const float* W_proj = (const float*)d_in[6];
    const float* b_proj = (const float*)d_in[7];
    (void)n_in; (void)out_size;
    int N = in_sizes[1];

    int init_blocks = WT_BLKS + STEP0_BLKS + (N + 255) / 256;
    k_init<<<init_blocks, 256>>>(batch, N, W_ih, W_hh, b_ih, b_hh);

    k_attn_part<<<B * SPLITS, 256>>>(x);
    k_attn_combine<<<B, 256>>>();

    for (int s = 1; s < 3; s++) {
        k_gemm_gates<<<dim3(FOURD / BN, B / BM, KSPLIT), 256>>>();
        k_lstm_ew<<<(B * D / 4 + 127) / 128, 128>>>();
        k_attn_part<<<B * SPLITS, 256>>>(x);
        k_attn_combine<<<B, 256>>>();
    }

    k_proj<<<(B * 256) / 8, 256>>>(W_proj, b_proj, (float*)d_out);
}

// round 11
// speedup vs baseline: 1.0607x; 1.0607x over previous
#include <cuda_runtime.h>
#include <math.h>
#include <stdint.h>

#define D      512
#define B      256
#define FOURD  2048
#define QS     1024   // 2*D
#define SPLITS 8
#define NW     8      // warps per attn block (256 threads)

#define BM 128
#define BN 128
#define BK 16
#define KSPLIT 8
#define KCH (QS / KSPLIT)   // 128
#define NIT (KCH / BK)      // 8

// ---- scratch (no allocations allowed) ----
__device__ float g_WcombT[QS * FOURD];  // [1024][2048] K-major (transposed combined weight)
__device__ float g_bsum[FOURD];
__device__ float g_qstar[B * QS];       // [h | r] row-major (attention/proj consumer)
__device__ float g_qstarT[QS * B];      // [1024][256] K-major (GEMM consumer)
__device__ float g_c[B * D];
__device__ float g_gpart[KSPLIT][B * FOURD];
__device__ int   g_segoff[B + 1];
// split-attention partials
__device__ float g_pm[B * SPLITS];
__device__ float g_pd[B * SPLITS];
__device__ float g_pr[B * SPLITS * D];

__device__ __forceinline__ float sigf(float v) { return 1.0f / (1.0f + expf(-v)); }

__device__ __forceinline__ void cp_async16(uint32_t dst_smem, const void* src) {
    asm volatile("cp.async.cg.shared.global [%0], [%1], 16;" :: "r"(dst_smem), "l"(src));
}

// ---------------- fused init: WcombT transpose + bsum + step0 + segscan ----------------
#define WT_BLKS  ((FOURD / 32) * (QS / 32))   // 2048
#define STEP0_BLKS (B * D / 256)              // 512
__global__ void k_init(const void* __restrict__ raw, int N,
                       const float* __restrict__ W_ih, const float* __restrict__ W_hh,
                       const float* __restrict__ b_ih, const float* __restrict__ b_hh) {
    __shared__ float s[32][33];
    int blk = blockIdx.x;
    int t = threadIdx.x;
    if (blk < WT_BLKS) {
        int nt = blk >> 5, kt = blk & 31;
        int tx = t & 31, ty = t >> 5;
        #pragma unroll
        for (int i = 0; i < 4; i++) {
            int n = nt * 32 + ty + i * 8;
            int k = kt * 32 + tx;
            float v = W_ih[(size_t)n * QS + k];
            if (k < D) v += W_hh[(size_t)n * D + k];
            s[ty + i * 8][tx] = v;
        }
        __syncthreads();
        #pragma unroll
        for (int i = 0; i < 4; i++) {
            int k = kt * 32 + ty + i * 8;
            int n = nt * 32 + tx;
            g_WcombT[(size_t)k * FOURD + n] = s[tx][ty + i * 8];
        }
        if (blk < 8) g_bsum[blk * 256 + t] = b_ih[blk * 256 + t] + b_hh[blk * 256 + t];
    } else if (blk < WT_BLKS + STEP0_BLKS) {
        int idx = (blk - WT_BLKS) * 256 + t;
        int j = idx & (D - 1);
        float gi = b_ih[j]         + b_hh[j];
        float gg = b_ih[2 * D + j] + b_hh[2 * D + j];
        float go = b_ih[3 * D + j] + b_hh[3 * D + j];
        float c  = sigf(gi) * tanhf(gg);
        float h  = sigf(go) * tanhf(c);
        int b = idx >> 9;
        g_c[idx] = c;
        g_qstar[b * QS + j] = h;
        g_qstarT[j * B + b] = h;
    } else {
        const int* p32 = (const int*)raw;
        bool is64 = (p32[N - 1] == 0) || (p32[N - 2] == 0);
        int i = (blk - WT_BLKS - STEP0_BLKS) * 256 + t;
        if (i >= N) return;
        int cur = is64 ? (int)((const long long*)raw)[i] : p32[i];
        if (i == 0) {
            for (int j = 0; j <= cur; j++) g_segoff[j] = 0;
        } else {
            int prev = is64 ? (int)((const long long*)raw)[i - 1] : p32[i - 1];
            for (int j = prev + 1; j <= cur; j++) g_segoff[j] = i;
        }
        if (i == N - 1) {
            for (int j = cur + 1; j <= B; j++) g_segoff[j] = N;
        }
    }
}

// ---------------- LSTM elementwise, float4, 128-thr blocks ----------------
__global__ void __launch_bounds__(128) k_lstm_ew() {
    int idx = blockIdx.x * 128 + threadIdx.x;   // over B*D/4
    if (idx >= B * D / 4) return;
    int b = idx >> 7;
    int j = (idx & 127) * 4;
    float4 gi = *(const float4*)&g_bsum[j];
    float4 gf = *(const float4*)&g_bsum[D + j];
    float4 gg = *(const float4*)&g_bsum[2 * D + j];
    float4 go = *(const float4*)&g_bsum[3 * D + j];
    #pragma unroll
    for (int z = 0; z < KSPLIT; z++) {
        const float* g = &g_gpart[z][(size_t)b * FOURD];
        float4 a = *(const float4*)&g[j];
        float4 f = *(const float4*)&g[D + j];
        float4 c = *(const float4*)&g[2 * D + j];
        float4 o = *(const float4*)&g[3 * D + j];
        gi.x += a.x; gi.y += a.y; gi.z += a.z; gi.w += a.w;
        gf.x += f.x; gf.y += f.y; gf.z += f.z; gf.w += f.w;
        gg.x += c.x; gg.y += c.y; gg.z += c.z; gg.w += c.w;
        go.x += o.x; go.y += o.y; go.z += o.z; go.w += o.w;
    }
    float4 cold = *(const float4*)&g_c[b * D + j];
    float4 cnew, hnew;
    cnew.x = sigf(gf.x) * cold.x + sigf(gi.x) * tanhf(gg.x);
    cnew.y = sigf(gf.y) * cold.y + sigf(gi.y) * tanhf(gg.y);
    cnew.z = sigf(gf.z) * cold.z + sigf(gi.z) * tanhf(gg.z);
    cnew.w = sigf(gf.w) * cold.w + sigf(gi.w) * tanhf(gg.w);
    hnew.x = sigf(go.x) * tanhf(cnew.x);
    hnew.y = sigf(go.y) * tanhf(cnew.y);
    hnew.z = sigf(go.z) * tanhf(cnew.z);
    hnew.w = sigf(go.w) * tanhf(cnew.w);
    *(float4*)&g_c[b * D + j] = cnew;
    *(float4*)&g_qstar[b * QS + j] = hnew;
    g_qstarT[(j + 0) * B + b] = hnew.x;
    g_qstarT[(j + 1) * B + b] = hnew.y;
    g_qstarT[(j + 2) * B + b] = hnew.z;
    g_qstarT[(j + 3) * B + b] = hnew.w;
}

// ---------------- gates GEMM v4 (round-9 champion, unchanged) ----------------
__global__ void __launch_bounds__(256, 2) k_gemm_gates() {
    __shared__ __align__(16) float As[3][BK][BM];
    __shared__ __align__(16) float Bs[3][BK][BN];
    int n0 = blockIdx.x * BN, m0 = blockIdx.y * BM, kc = blockIdx.z * KCH;
    int t = threadIdx.x;
    int tx = t & 15, ty = t >> 4;

    unsigned long long acc2[8][4];
    #pragma unroll
    for (int i = 0; i < 8; i++)
        #pragma unroll
        for (int j = 0; j < 4; j++) acc2[i][j] = 0ull;

    int kr0 = t >> 5, kr1 = kr0 + 8;
    int mq  = (t & 31) * 4;

    const float* srcA = g_qstarT + (size_t)kc * B;
    const float* srcB = g_WcombT + (size_t)kc * FOURD;

    #pragma unroll
    for (int s = 0; s < 2; s++) {
        int kof = s * BK;
        cp_async16(__cvta_generic_to_shared(&As[s][kr0][mq]), srcA + (size_t)(kof + kr0) * B + m0 + mq);
        cp_async16(__cvta_generic_to_shared(&As[s][kr1][mq]), srcA + (size_t)(kof + kr1) * B + m0 + mq);
        cp_async16(__cvta_generic_to_shared(&Bs[s][kr0][mq]), srcB + (size_t)(kof + kr0) * FOURD + n0 + mq);
        cp_async16(__cvta_generic_to_shared(&Bs[s][kr1][mq]), srcB + (size_t)(kof + kr1) * FOURD + n0 + mq);
        asm volatile("cp.async.commit_group;");
    }

    #pragma unroll
    for (int it = 0; it < NIT; it++) {
        if (it < NIT - 1) asm volatile("cp.async.wait_group 1;");
        else              asm volatile("cp.async.wait_group 0;");
        __syncthreads();
        if (it + 2 < NIT) {
            int st = (it + 2) % 3;
            int kof = (it + 2) * BK;
            cp_async16(__cvta_generic_to_shared(&As[st][kr0][mq]), srcA + (size_t)(kof + kr0) * B + m0 + mq);
            cp_async16(__cvta_generic_to_shared(&As[st][kr1][mq]), srcA + (size_t)(kof + kr1) * B + m0 + mq);
            cp_async16(__cvta_generic_to_shared(&Bs[st][kr0][mq]), srcB + (size_t)(kof + kr0) * FOURD + n0 + mq);
            cp_async16(__cvta_generic_to_shared(&Bs[st][kr1][mq]), srcB + (size_t)(kof + kr1) * FOURD + n0 + mq);
            asm volatile("cp.async.commit_group;");
        }
        int cb = it % 3;
        #pragma unroll
        for (int kk = 0; kk < BK; kk++) {
            float a[8];
            *(float4*)(a)     = *(const float4*)&As[cb][kk][ty * 8];
            *(float4*)(a + 4) = *(const float4*)&As[cb][kk][ty * 8 + 4];
            unsigned long long b2[4];
            {
                ulonglong2 bl0 = *(const ulonglong2*)&Bs[cb][kk][tx * 8];
                ulonglong2 bl1 = *(const ulonglong2*)&Bs[cb][kk][tx * 8 + 4];
                b2[0] = bl0.x; b2[1] = bl0.y; b2[2] = bl1.x; b2[3] = bl1.y;
            }
            #pragma unroll
            for (int i = 0; i < 8; i++) {
                unsigned long long a2;
                asm("mov.b64 %0, {%1, %1};" : "=l"(a2) : "r"(__float_as_uint(a[i])));
                #pragma unroll
                for (int j = 0; j < 4; j++)
                    asm("fma.rn.f32x2 %0, %1, %2, %0;"
                        : "+l"(acc2[i][j]) : "l"(a2), "l"(b2[j]));
            }
        }
    }
    #pragma unroll
    for (int i = 0; i < 8; i++) {
        int mrow = m0 + ty * 8 + i;
        unsigned long long* dst =
            (unsigned long long*)&g_gpart[blockIdx.z][(size_t)mrow * FOURD + n0 + tx * 8];
        *(ulonglong2*)(dst)     = make_ulonglong2(acc2[i][0], acc2[i][1]);
        *(ulonglong2*)(dst + 2) = make_ulonglong2(acc2[i][2], acc2[i][3]);
    }
}

// ---------------- split segment attention: round-9 shape, q kept in SHARED (not regs)
// ---------------- so regs fit 64 -> 4 blocks/SM ----------------
__global__ void __launch_bounds__(256, 4) k_attn_part(const float* __restrict__ x) {
    __shared__ __align__(16) float q_sh[D];
    __shared__ __align__(16) float rsh[NW][D];
    __shared__ float msh[NW], dsh[NW];

    int b  = blockIdx.x / SPLITS;
    int sp = blockIdx.x % SPLITS;
    int t = threadIdx.x;
    int w = t >> 5, lane = t & 31;

    int segs = g_segoff[b], sege = g_segoff[b + 1];
    int total = sege - segs;
    int start = segs + (int)(((long long)total * sp) / SPLITS);
    int end   = segs + (int)(((long long)total * (sp + 1)) / SPLITS);

    q_sh[t]       = g_qstar[b * QS + t];
    q_sh[t + 256] = g_qstar[b * QS + t + 256];
    __syncthreads();

    float m = -INFINITY, d = 0.0f;
    float r[16];
    #pragma unroll
    for (int j = 0; j < 16; j++) r[j] = 0.0f;

    int n = start + w;
    float4 xb0, xb1, xb2, xb3;
    if (n < end) {
        const float* p = x + (size_t)n * D;
        xb0 = ((const float4*)(p      ))[lane];
        xb1 = ((const float4*)(p + 128))[lane];
        xb2 = ((const float4*)(p + 256))[lane];
        xb3 = ((const float4*)(p + 384))[lane];
    }
    while (n < end) {
        float4 c0 = xb0, c1 = xb1, c2 = xb2, c3 = xb3;
        int nn = n + NW;
        if (nn < end) {
            const float* p = x + (size_t)nn * D;
            xb0 = ((const float4*)(p      ))[lane];
            xb1 = ((const float4*)(p + 128))[lane];
            xb2 = ((const float4*)(p + 256))[lane];
            xb3 = ((const float4*)(p + 384))[lane];
        }
        // dot with q loaded transiently from shared (keeps register count <= 64)
        float s;
        {
            float4 q0 = *(const float4*)&q_sh[          lane * 4];
            float4 q1 = *(const float4*)&q_sh[128 +     lane * 4];
            float4 q2 = *(const float4*)&q_sh[256 +     lane * 4];
            float4 q3 = *(const float4*)&q_sh[384 +     lane * 4];
            s = c0.x * q0.x + c0.y * q0.y + c0.z * q0.z + c0.w * q0.w
              + c1.x * q1.x + c1.y * q1.y + c1.z * q1.z + c1.w * q1.w
              + c2.x * q2.x + c2.y * q2.y + c2.z * q2.z + c2.w * q2.w
              + c3.x * q3.x + c3.y * q3.y + c3.z * q3.z + c3.w * q3.w;
        }
        #pragma unroll
        for (int o = 16; o > 0; o >>= 1) s += __shfl_xor_sync(0xffffffffu, s, o);

        if (s > m) {
            float al = __expf(m - s);   // first iteration: exp(-inf) = 0
            d = d * al + 1.0f;
            r[0]  = r[0]  * al + c0.x;  r[1]  = r[1]  * al + c0.y;
            r[2]  = r[2]  * al + c0.z;  r[3]  = r[3]  * al + c0.w;
            r[4]  = r[4]  * al + c1.x;  r[5]  = r[5]  * al + c1.y;
            r[6]  = r[6]  * al + c1.z;  r[7]  = r[7]  * al + c1.w;
            r[8]  = r[8]  * al + c2.x;  r[9]  = r[9]  * al + c2.y;
            r[10] = r[10] * al + c2.z;  r[11] = r[11] * al + c2.w;
            r[12] = r[12] * al + c3.x;  r[13] = r[13] * al + c3.y;
            r[14] = r[14] * al + c3.z;  r[15] = r[15] * al + c3.w;
            m = s;
        } else {
            float wv = __expf(s - m);
            d += wv;
            r[0]  += wv * c0.x;  r[1]  += wv * c0.y;  r[2]  += wv * c0.z;  r[3]  += wv * c0.w;
            r[4]  += wv * c1.x;  r[5]  += wv * c1.y;  r[6]  += wv * c1.z;  r[7]  += wv * c1.w;
            r[8]  += wv * c2.x;  r[9]  += wv * c2.y;  r[10] += wv * c2.z;  r[11] += wv * c2.w;
            r[12] += wv * c3.x;  r[13] += wv * c3.y;  r[14] += wv * c3.z;  r[15] += wv * c3.w;
        }
        n = nn;
    }

    // per-warp partials to shared (canonical column order)
    if (lane == 0) { msh[w] = m; dsh[w] = d; }
    #pragma unroll
    for (int c = 0; c < 4; c++)
        *(float4*)&rsh[w][c * 128 + lane * 4] =
            make_float4(r[c * 4], r[c * 4 + 1], r[c * 4 + 2], r[c * 4 + 3]);
    __syncthreads();

    // block combine: thread t owns cols t and t+256
    float M = msh[0];
    #pragma unroll
    for (int p = 1; p < NW; p++) M = fmaxf(M, msh[p]);
    float Mg = isfinite(M) ? M : 0.0f;
    float dd = 0.0f, r0 = 0.0f, r1 = 0.0f;
    #pragma unroll
    for (int p = 0; p < NW; p++) {
        float sc = __expf(msh[p] - Mg);
        dd += dsh[p] * sc;
        r0 += rsh[p][t] * sc;
        r1 += rsh[p][t + 256] * sc;
    }
    int pid = b * SPLITS + sp;
    g_pr[(size_t)pid * D + t]       = r0;
    g_pr[(size_t)pid * D + t + 256] = r1;
    if (t == 0) { g_pm[pid] = M; g_pd[pid] = dd; }
}

// ---------------- combine split partials -> r in g_qstar (+ transposed copy) ----------------
__global__ void k_attn_combine() {
    __shared__ float sm[SPLITS], sd[SPLITS];
    int b = blockIdx.x, t = threadIdx.x;
    if (t < SPLITS) {
        sm[t] = g_pm[b * SPLITS + t];
        sd[t] = g_pd[b * SPLITS + t];
    }
    __syncthreads();
    float M = -INFINITY;
    #pragma unroll
    for (int p = 0; p < SPLITS; p++) M = fmaxf(M, sm[p]);
    if (!isfinite(M)) M = 0.0f;
    float denom = 0.0f;
    float scale[SPLITS];
    #pragma unroll
    for (int p = 0; p < SPLITS; p++) {
        scale[p] = expf(sm[p] - M);
        denom += sd[p] * scale[p];
    }
    float inv = 1.0f / (denom + 1e-16f);
    float r0 = 0.0f, r1 = 0.0f;
    #pragma unroll
    for (int p = 0; p < SPLITS; p++) {
        const float* pr = g_pr + (size_t)(b * SPLITS + p) * D;
        r0 += pr[t]       * scale[p];
        r1 += pr[t + 256] * scale[p];
    }
    r0 *= inv; r1 *= inv;
    g_qstar[b * QS + D + t]        = r0;
    g_qstar[b * QS + D + t + 256]  = r1;
    g_qstarT[(D + t) * B + b]       = r0;
    g_qstarT[(D + t + 256) * B + b] = r1;
}

// ---------------- projection ----------------
__global__ void k_proj(const float* __restrict__ Wp, const float* __restrict__ bp,
                       float* __restrict__ out) {
    int gw = (blockIdx.x * 256 + threadIdx.x) >> 5;
    int lane = threadIdx.x & 31;
    int bb = gw >> 8, o = gw & 255;
    const float* qr = g_qstar + bb * QS;
    const float* wr = Wp + o * QS;
    float s = 0.0f;
    #pragma unroll
    for (int it = 0; it < QS / 128; it++) {
        int k = lane * 4 + it * 128;
        float4 a = *(const float4*)(qr + k);
        float4 w = *(const float4*)(wr + k);
        s += a.x * w.x + a.y * w.y + a.z * w.z + a.w * w.w;
    }
    #pragma unroll
    for (int off = 16; off > 0; off >>= 1) s += __shfl_xor_sync(0xffffffffu, s, off);
    if (lane == 0) out[gw] = s + bp[o];
}

// ---------------- launch ----------------
extern "C" void kernel_launch(void* const* d_in, const int* in_sizes, int n_in,
                              void* d_out, int out_size) {
    const float* x      = (const float*)d_in[0];
    const void*  batch  = d_in[1];
    const float* W_ih   = (const float*)d_in[2];
    const float* W_hh   = (const float*)d_in[3];
    const float* b_ih   = (const float*)d_in[4];
    const float* b_hh   = (const float*)d_in[5];
    const float* W_proj = (const float*)d_in[6];
    const float* b_proj = (const float*)d_in[7];
    (void)n_in; (void)out_size;
    int N = in_sizes[1];

    int init_blocks = WT_BLKS + STEP0_BLKS + (N + 255) / 256;
    k_init<<<init_blocks, 256>>>(batch, N, W_ih, W_hh, b_ih, b_hh);

    k_attn_part<<<B * SPLITS, 256>>>(x);
    k_attn_combine<<<B, 256>>>();

    for (int s = 1; s < 3; s++) {
        k_gemm_gates<<<dim3(FOURD / BN, B / BM, KSPLIT), 256>>>();
        k_lstm_ew<<<(B * D / 4 + 127) / 128, 128>>>();
        k_attn_part<<<B * SPLITS, 256>>>(x);
        k_attn_combine<<<B, 256>>>();
    }

    k_proj<<<(B * 256) / 8, 256>>>(W_proj, b_proj, (float*)d_out);
}

// round 12
// speedup vs baseline: 1.1129x; 1.0492x over previous
#include <cuda_runtime.h>
#include <math.h>
#include <stdint.h>

#define D      512
#define B      256
#define FOURD  2048
#define QS     1024   // 2*D
#define SPLITS 8
#define NW     8      // warps per attn block (256 threads)
#define NITEMS (B * SPLITS)
#define ATTN_BLOCKS 444   // 148 SMs * 3 resident CTAs

#define BM 128
#define BN 128
#define BK 16
#define KSPLIT 8
#define KCH (QS / KSPLIT)   // 128
#define NIT (KCH / BK)      // 8

// ---- scratch (no allocations allowed) ----
__device__ float g_WcombT[QS * FOURD];  // [1024][2048] K-major (transposed combined weight)
__device__ float g_bsum[FOURD];
__device__ float g_qstar[B * QS];       // [h | r] row-major (attention/proj consumer)
__device__ float g_qstarT[QS * B];      // [1024][256] K-major (GEMM consumer)
__device__ float g_c[B * D];
__device__ float g_gpart[KSPLIT][B * FOURD];
__device__ int   g_segoff[B + 1];
// split-attention partials + per-pass work counters (zeroed by k_init every launch)
__device__ float g_pm[B * SPLITS];
__device__ float g_pd[B * SPLITS];
__device__ float g_pr[B * SPLITS * D];
__device__ int   g_work[4];

__device__ __forceinline__ float sigf(float v) { return 1.0f / (1.0f + expf(-v)); }

__device__ __forceinline__ void cp_async16(uint32_t dst_smem, const void* src) {
    asm volatile("cp.async.cg.shared.global [%0], [%1], 16;" :: "r"(dst_smem), "l"(src));
}

// ---------------- fused init: WcombT transpose + bsum + step0 + segscan + counters ----------------
#define WT_BLKS  ((FOURD / 32) * (QS / 32))   // 2048
#define STEP0_BLKS (B * D / 256)              // 512
__global__ void k_init(const void* __restrict__ raw, int N,
                       const float* __restrict__ W_ih, const float* __restrict__ W_hh,
                       const float* __restrict__ b_ih, const float* __restrict__ b_hh) {
    __shared__ float s[32][33];
    int blk = blockIdx.x;
    int t = threadIdx.x;
    if (blk < WT_BLKS) {
        if (blk == 0 && t < 4) g_work[t] = 0;   // reset attention work queues (replay-safe)
        int nt = blk >> 5, kt = blk & 31;
        int tx = t & 31, ty = t >> 5;
        #pragma unroll
        for (int i = 0; i < 4; i++) {
            int n = nt * 32 + ty + i * 8;
            int k = kt * 32 + tx;
            float v = W_ih[(size_t)n * QS + k];
            if (k < D) v += W_hh[(size_t)n * D + k];
            s[ty + i * 8][tx] = v;
        }
        __syncthreads();
        #pragma unroll
        for (int i = 0; i < 4; i++) {
            int k = kt * 32 + ty + i * 8;
            int n = nt * 32 + tx;
            g_WcombT[(size_t)k * FOURD + n] = s[tx][ty + i * 8];
        }
        if (blk < 8) g_bsum[blk * 256 + t] = b_ih[blk * 256 + t] + b_hh[blk * 256 + t];
    } else if (blk < WT_BLKS + STEP0_BLKS) {
        int idx = (blk - WT_BLKS) * 256 + t;
        int j = idx & (D - 1);
        float gi = b_ih[j]         + b_hh[j];
        float gg = b_ih[2 * D + j] + b_hh[2 * D + j];
        float go = b_ih[3 * D + j] + b_hh[3 * D + j];
        float c  = sigf(gi) * tanhf(gg);
        float h  = sigf(go) * tanhf(c);
        int b = idx >> 9;
        g_c[idx] = c;
        g_qstar[b * QS + j] = h;
        g_qstarT[j * B + b] = h;
    } else {
        const int* p32 = (const int*)raw;
        bool is64 = (p32[N - 1] == 0) || (p32[N - 2] == 0);
        int i = (blk - WT_BLKS - STEP0_BLKS) * 256 + t;
        if (i >= N) return;
        int cur = is64 ? (int)((const long long*)raw)[i] : p32[i];
        if (i == 0) {
            for (int j = 0; j <= cur; j++) g_segoff[j] = 0;
        } else {
            int prev = is64 ? (int)((const long long*)raw)[i - 1] : p32[i - 1];
            for (int j = prev + 1; j <= cur; j++) g_segoff[j] = i;
        }
        if (i == N - 1) {
            for (int j = cur + 1; j <= B; j++) g_segoff[j] = N;
        }
    }
}

// ---------------- LSTM elementwise, float4, 128-thr blocks ----------------
__global__ void __launch_bounds__(128) k_lstm_ew() {
    int idx = blockIdx.x * 128 + threadIdx.x;   // over B*D/4
    if (idx >= B * D / 4) return;
    int b = idx >> 7;
    int j = (idx & 127) * 4;
    float4 gi = *(const float4*)&g_bsum[j];
    float4 gf = *(const float4*)&g_bsum[D + j];
    float4 gg = *(const float4*)&g_bsum[2 * D + j];
    float4 go = *(const float4*)&g_bsum[3 * D + j];
    #pragma unroll
    for (int z = 0; z < KSPLIT; z++) {
        const float* g = &g_gpart[z][(size_t)b * FOURD];
        float4 a = *(const float4*)&g[j];
        float4 f = *(const float4*)&g[D + j];
        float4 c = *(const float4*)&g[2 * D + j];
        float4 o = *(const float4*)&g[3 * D + j];
        gi.x += a.x; gi.y += a.y; gi.z += a.z; gi.w += a.w;
        gf.x += f.x; gf.y += f.y; gf.z += f.z; gf.w += f.w;
        gg.x += c.x; gg.y += c.y; gg.z += c.z; gg.w += c.w;
        go.x += o.x; go.y += o.y; go.z += o.z; go.w += o.w;
    }
    float4 cold = *(const float4*)&g_c[b * D + j];
    float4 cnew, hnew;
    cnew.x = sigf(gf.x) * cold.x + sigf(gi.x) * tanhf(gg.x);
    cnew.y = sigf(gf.y) * cold.y + sigf(gi.y) * tanhf(gg.y);
    cnew.z = sigf(gf.z) * cold.z + sigf(gi.z) * tanhf(gg.z);
    cnew.w = sigf(gf.w) * cold.w + sigf(gi.w) * tanhf(gg.w);
    hnew.x = sigf(go.x) * tanhf(cnew.x);
    hnew.y = sigf(go.y) * tanhf(cnew.y);
    hnew.z = sigf(go.z) * tanhf(cnew.z);
    hnew.w = sigf(go.w) * tanhf(cnew.w);
    *(float4*)&g_c[b * D + j] = cnew;
    *(float4*)&g_qstar[b * QS + j] = hnew;
    g_qstarT[(j + 0) * B + b] = hnew.x;
    g_qstarT[(j + 1) * B + b] = hnew.y;
    g_qstarT[(j + 2) * B + b] = hnew.z;
    g_qstarT[(j + 3) * B + b] = hnew.w;
}

// ---------------- gates GEMM v4 (round-9 champion, unchanged) ----------------
__global__ void __launch_bounds__(256, 2) k_gemm_gates() {
    __shared__ __align__(16) float As[3][BK][BM];
    __shared__ __align__(16) float Bs[3][BK][BN];
    int n0 = blockIdx.x * BN, m0 = blockIdx.y * BM, kc = blockIdx.z * KCH;
    int t = threadIdx.x;
    int tx = t & 15, ty = t >> 4;

    unsigned long long acc2[8][4];
    #pragma unroll
    for (int i = 0; i < 8; i++)
        #pragma unroll
        for (int j = 0; j < 4; j++) acc2[i][j] = 0ull;

    int kr0 = t >> 5, kr1 = kr0 + 8;
    int mq  = (t & 31) * 4;

    const float* srcA = g_qstarT + (size_t)kc * B;
    const float* srcB = g_WcombT + (size_t)kc * FOURD;

    #pragma unroll
    for (int s = 0; s < 2; s++) {
        int kof = s * BK;
        cp_async16(__cvta_generic_to_shared(&As[s][kr0][mq]), srcA + (size_t)(kof + kr0) * B + m0 + mq);
        cp_async16(__cvta_generic_to_shared(&As[s][kr1][mq]), srcA + (size_t)(kof + kr1) * B + m0 + mq);
        cp_async16(__cvta_generic_to_shared(&Bs[s][kr0][mq]), srcB + (size_t)(kof + kr0) * FOURD + n0 + mq);
        cp_async16(__cvta_generic_to_shared(&Bs[s][kr1][mq]), srcB + (size_t)(kof + kr1) * FOURD + n0 + mq);
        asm volatile("cp.async.commit_group;");
    }

    #pragma unroll
    for (int it = 0; it < NIT; it++) {
        if (it < NIT - 1) asm volatile("cp.async.wait_group 1;");
        else              asm volatile("cp.async.wait_group 0;");
        __syncthreads();
        if (it + 2 < NIT) {
            int st = (it + 2) % 3;
            int kof = (it + 2) * BK;
            cp_async16(__cvta_generic_to_shared(&As[st][kr0][mq]), srcA + (size_t)(kof + kr0) * B + m0 + mq);
            cp_async16(__cvta_generic_to_shared(&As[st][kr1][mq]), srcA + (size_t)(kof + kr1) * B + m0 + mq);
            cp_async16(__cvta_generic_to_shared(&Bs[st][kr0][mq]), srcB + (size_t)(kof + kr0) * FOURD + n0 + mq);
            cp_async16(__cvta_generic_to_shared(&Bs[st][kr1][mq]), srcB + (size_t)(kof + kr1) * FOURD + n0 + mq);
            asm volatile("cp.async.commit_group;");
        }
        int cb = it % 3;
        #pragma unroll
        for (int kk = 0; kk < BK; kk++) {
            float a[8];
            *(float4*)(a)     = *(const float4*)&As[cb][kk][ty * 8];
            *(float4*)(a + 4) = *(const float4*)&As[cb][kk][ty * 8 + 4];
            unsigned long long b2[4];
            {
                ulonglong2 bl0 = *(const ulonglong2*)&Bs[cb][kk][tx * 8];
                ulonglong2 bl1 = *(const ulonglong2*)&Bs[cb][kk][tx * 8 + 4];
                b2[0] = bl0.x; b2[1] = bl0.y; b2[2] = bl1.x; b2[3] = bl1.y;
            }
            #pragma unroll
            for (int i = 0; i < 8; i++) {
                unsigned long long a2;
                asm("mov.b64 %0, {%1, %1};" : "=l"(a2) : "r"(__float_as_uint(a[i])));
                #pragma unroll
                for (int j = 0; j < 4; j++)
                    asm("fma.rn.f32x2 %0, %1, %2, %0;"
                        : "+l"(acc2[i][j]) : "l"(a2), "l"(b2[j]));
            }
        }
    }
    #pragma unroll
    for (int i = 0; i < 8; i++) {
        int mrow = m0 + ty * 8 + i;
        unsigned long long* dst =
            (unsigned long long*)&g_gpart[blockIdx.z][(size_t)mrow * FOURD + n0 + tx * 8];
        *(ulonglong2*)(dst)     = make_ulonglong2(acc2[i][0], acc2[i][1]);
        *(ulonglong2*)(dst + 2) = make_ulonglong2(acc2[i][2], acc2[i][3]);
    }
}

// ---------------- persistent split segment attention (round-9 inner loop, work queue) ----------------
// 444 resident blocks pull (b,sp) items from g_work[pass]; per-item math identical to round 9.
__global__ void __launch_bounds__(256) k_attn_part(const float* __restrict__ x, int pass) {
    __shared__ __align__(16) float q_sh[D];
    __shared__ __align__(16) float rsh[NW][D];
    __shared__ float msh[NW], dsh[NW];
    __shared__ int s_item;

    int t = threadIdx.x;
    int w = t >> 5, lane = t & 31;

    for (;;) {
        __syncthreads();   // previous item's shared state fully consumed
        if (t == 0) s_item = atomicAdd(&g_work[pass], 1);
        __syncthreads();
        int item = s_item;
        if (item >= NITEMS) return;
        int b  = item >> 3;       // SPLITS = 8
        int sp = item & 7;

        int segs = g_segoff[b], sege = g_segoff[b + 1];
        int total = sege - segs;
        int start = segs + (int)(((long long)total * sp) / SPLITS);
        int end   = segs + (int)(((long long)total * (sp + 1)) / SPLITS);

        q_sh[t]       = g_qstar[b * QS + t];
        q_sh[t + 256] = g_qstar[b * QS + t + 256];
        __syncthreads();

        float qr[16];
        #pragma unroll
        for (int c = 0; c < 4; c++) {
            float4 qv = *(const float4*)&q_sh[c * 128 + lane * 4];
            qr[c * 4 + 0] = qv.x; qr[c * 4 + 1] = qv.y;
            qr[c * 4 + 2] = qv.z; qr[c * 4 + 3] = qv.w;
        }

        float m = -INFINITY, d = 0.0f;
        float r[16];
        #pragma unroll
        for (int j = 0; j < 16; j++) r[j] = 0.0f;

        int n = start + w;
        float4 xb0, xb1, xb2, xb3;
        if (n < end) {
            const float* p = x + (size_t)n * D;
            xb0 = ((const float4*)(p      ))[lane];
            xb1 = ((const float4*)(p + 128))[lane];
            xb2 = ((const float4*)(p + 256))[lane];
            xb3 = ((const float4*)(p + 384))[lane];
        }
        while (n < end) {
            float4 c0 = xb0, c1 = xb1, c2 = xb2, c3 = xb3;
            int nn = n + NW;
            if (nn < end) {
                const float* p = x + (size_t)nn * D;
                xb0 = ((const float4*)(p      ))[lane];
                xb1 = ((const float4*)(p + 128))[lane];
                xb2 = ((const float4*)(p + 256))[lane];
                xb3 = ((const float4*)(p + 384))[lane];
            }
            float s = c0.x * qr[0]  + c0.y * qr[1]  + c0.z * qr[2]  + c0.w * qr[3]
                    + c1.x * qr[4]  + c1.y * qr[5]  + c1.z * qr[6]  + c1.w * qr[7]
                    + c2.x * qr[8]  + c2.y * qr[9]  + c2.z * qr[10] + c2.w * qr[11]
                    + c3.x * qr[12] + c3.y * qr[13] + c3.z * qr[14] + c3.w * qr[15];
            #pragma unroll
            for (int o = 16; o > 0; o >>= 1) s += __shfl_xor_sync(0xffffffffu, s, o);

            if (s > m) {
                float al = __expf(m - s);   // first iteration: exp(-inf) = 0
                d = d * al + 1.0f;
                r[0]  = r[0]  * al + c0.x;  r[1]  = r[1]  * al + c0.y;
                r[2]  = r[2]  * al + c0.z;  r[3]  = r[3]  * al + c0.w;
                r[4]  = r[4]  * al + c1.x;  r[5]  = r[5]  * al + c1.y;
                r[6]  = r[6]  * al + c1.z;  r[7]  = r[7]  * al + c1.w;
                r[8]  = r[8]  * al + c2.x;  r[9]  = r[9]  * al + c2.y;
                r[10] = r[10] * al + c2.z;  r[11] = r[11] * al + c2.w;
                r[12] = r[12] * al + c3.x;  r[13] = r[13] * al + c3.y;
                r[14] = r[14] * al + c3.z;  r[15] = r[15] * al + c3.w;
                m = s;
            } else {
                float wv = __expf(s - m);
                d += wv;
                r[0]  += wv * c0.x;  r[1]  += wv * c0.y;  r[2]  += wv * c0.z;  r[3]  += wv * c0.w;
                r[4]  += wv * c1.x;  r[5]  += wv * c1.y;  r[6]  += wv * c1.z;  r[7]  += wv * c1.w;
                r[8]  += wv * c2.x;  r[9]  += wv * c2.y;  r[10] += wv * c2.z;  r[11] += wv * c2.w;
                r[12] += wv * c3.x;  r[13] += wv * c3.y;  r[14] += wv * c3.z;  r[15] += wv * c3.w;
            }
            n = nn;
        }

        // per-warp partials to shared (canonical column order)
        if (lane == 0) { msh[w] = m; dsh[w] = d; }
        #pragma unroll
        for (int c = 0; c < 4; c++)
            *(float4*)&rsh[w][c * 128 + lane * 4] =
                make_float4(r[c * 4], r[c * 4 + 1], r[c * 4 + 2], r[c * 4 + 3]);
        __syncthreads();

        // block combine: thread t owns cols t and t+256
        float M = msh[0];
        #pragma unroll
        for (int p = 1; p < NW; p++) M = fmaxf(M, msh[p]);
        float Mg = isfinite(M) ? M : 0.0f;
        float dd = 0.0f, r0 = 0.0f, r1 = 0.0f;
        #pragma unroll
        for (int p = 0; p < NW; p++) {
            float sc = __expf(msh[p] - Mg);
            dd += dsh[p] * sc;
            r0 += rsh[p][t] * sc;
            r1 += rsh[p][t + 256] * sc;
        }
        int pid = b * SPLITS + sp;
        g_pr[(size_t)pid * D + t]       = r0;
        g_pr[(size_t)pid * D + t + 256] = r1;
        if (t == 0) { g_pm[pid] = M; g_pd[pid] = dd; }
    }
}

// ---------------- combine split partials -> r in g_qstar (+ transposed copy) ----------------
__global__ void k_attn_combine() {
    __shared__ float sm[SPLITS], sd[SPLITS];
    int b = blockIdx.x, t = threadIdx.x;
    if (t < SPLITS) {
        sm[t] = g_pm[b * SPLITS + t];
        sd[t] = g_pd[b * SPLITS + t];
    }
    __syncthreads();
    float M = -INFINITY;
    #pragma unroll
    for (int p = 0; p < SPLITS; p++) M = fmaxf(M, sm[p]);
    if (!isfinite(M)) M = 0.0f;
    float denom = 0.0f;
    float scale[SPLITS];
    #pragma unroll
    for (int p = 0; p < SPLITS; p++) {
        scale[p] = expf(sm[p] - M);
        denom += sd[p] * scale[p];
    }
    float inv = 1.0f / (denom + 1e-16f);
    float r0 = 0.0f, r1 = 0.0f;
    #pragma unroll
    for (int p = 0; p < SPLITS; p++) {
        const float* pr = g_pr + (size_t)(b * SPLITS + p) * D;
        r0 += pr[t]       * scale[p];
        r1 += pr[t + 256] * scale[p];
    }
    r0 *= inv; r1 *= inv;
    g_qstar[b * QS + D + t]        = r0;
    g_qstar[b * QS + D + t + 256]  = r1;
    g_qstarT[(D + t) * B + b]       = r0;
    g_qstarT[(D + t + 256) * B + b] = r1;
}

// ---------------- projection ----------------
__global__ void k_proj(const float* __restrict__ Wp, const float* __restrict__ bp,
                       float* __restrict__ out) {
    int gw = (blockIdx.x * 256 + threadIdx.x) >> 5;
    int lane = threadIdx.x & 31;
    int bb = gw >> 8, o = gw & 255;
    const float* qr = g_qstar + bb * QS;
    const float* wr = Wp + o * QS;
    float s = 0.0f;
    #pragma unroll
    for (int it = 0; it < QS / 128; it++) {
        int k = lane * 4 + it * 128;
        float4 a = *(const float4*)(qr + k);
        float4 w = *(const float4*)(wr + k);
        s += a.x * w.x + a.y * w.y + a.z * w.z + a.w * w.w;
    }
    #pragma unroll
    for (int off = 16; off > 0; off >>= 1) s += __shfl_xor_sync(0xffffffffu, s, off);
    if (lane == 0) out[gw] = s + bp[o];
}

// ---------------- launch ----------------
extern "C" void kernel_launch(void* const* d_in, const int* in_sizes, int n_in,
                              void* d_out, int out_size) {
    const float* x      = (const float*)d_in[0];
    const void*  batch  = d_in[1];
    const float* W_ih   = (const float*)d_in[2];
    const float* W_hh   = (const float*)d_in[3];
    const float* b_ih   = (const float*)d_in[4];
    const float* b_hh   = (const float*)d_in[5];
    const float* W_proj = (const float*)d_in[6];
    const float* b_proj = (const float*)d_in[7];
    (void)n_in; (void)out_size;
    int N = in_sizes[1];

    int init_blocks = WT_BLKS + STEP0_BLKS + (N + 255) / 256;
    k_init<<<init_blocks, 256>>>(batch, N, W_ih, W_hh, b_ih, b_hh);

    k_attn_part<<<ATTN_BLOCKS, 256>>>(x, 0);
    k_attn_combine<<<B, 256>>>();

    for (int s = 1; s < 3; s++) {
        k_gemm_gates<<<dim3(FOURD / BN, B / BM, KSPLIT), 256>>>();
        k_lstm_ew<<<(B * D / 4 + 127) / 128, 128>>>();
        k_attn_part<<<ATTN_BLOCKS, 256>>>(x, s);
        k_attn_combine<<<B, 256>>>();
    }

    k_proj<<<(B * 256) / 8, 256>>>(W_proj, b_proj, (float*)d_out);
}